// round 1
// baseline (speedup 1.0000x reference)
#include <cuda_runtime.h>
#include <math.h>

#define NN 10000
#define NE 320000
#define DD 256
#define NL 3

// ---------------- scratch (static device allocations; no runtime alloc) ----
__device__ float g_hA[NN * DD];
__device__ float g_hB[NN * DD];
__device__ float g_t[NN * DD];          // t = h @ (wq wk^T)
__device__ float g_u[NN * DD];          // u = h @ (wv wp)
__device__ float g_M[NL * DD * DD];     // wq @ wk^T per layer
__device__ float g_wvp[NL * DD * DD];   // wv @ wp per layer
__device__ int   g_deg[NN];
__device__ int   g_off[NN + 1];
__device__ int   g_cur[NN];
__device__ int   g_srcs[NE];            // src indices sorted (grouped) by dst

// ---------------- CSR build ------------------------------------------------
__global__ void k_init() {
    int i = blockIdx.x * blockDim.x + threadIdx.x;
    if (i < NN) { g_deg[i] = 0; g_cur[i] = 0; }
}

__global__ void k_hist(const int* __restrict__ dst) {
    int e = blockIdx.x * blockDim.x + threadIdx.x;
    if (e < NE) atomicAdd(&g_deg[dst[e]], 1);
}

// single-block exclusive scan of g_deg -> g_off (10000 elements)
__global__ void k_scan() {
    __shared__ int ws[32];
    int tid = threadIdx.x, lane = tid & 31, wid = tid >> 5;
    int carry = 0;
    for (int base = 0; base < NN; base += 1024) {
        int x = (base + tid < NN) ? g_deg[base + tid] : 0;
        int v = x;
        #pragma unroll
        for (int o = 1; o < 32; o <<= 1) {
            int y = __shfl_up_sync(0xffffffffu, v, o);
            if (lane >= o) v += y;
        }
        if (lane == 31) ws[wid] = v;
        __syncthreads();
        if (tid < 32) {
            int w = ws[tid];
            #pragma unroll
            for (int o = 1; o < 32; o <<= 1) {
                int y = __shfl_up_sync(0xffffffffu, w, o);
                if (tid >= o) w += y;
            }
            ws[tid] = w;
        }
        __syncthreads();
        int add = wid ? ws[wid - 1] : 0;
        if (base + tid < NN) g_off[base + tid] = carry + add + v - x;
        int tot = ws[31];
        __syncthreads();
        carry += tot;
    }
    if (tid == 0) g_off[NN] = carry;
}

__global__ void k_scatter(const int* __restrict__ src, const int* __restrict__ dst) {
    int e = blockIdx.x * blockDim.x + threadIdx.x;
    if (e < NE) {
        int d = dst[e];
        int pos = g_off[d] + atomicAdd(&g_cur[d], 1);
        g_srcs[pos] = src[e];
    }
}

// ---------------- tiny 256x256x256 GEMMs (weight folding) ------------------
// z in [0,3): g_M[z]   = wq[z] @ wk[z]^T
// z in [3,6): g_wvp[z-3] = wv[z-3] @ wp[z-3]
__global__ __launch_bounds__(256) void k_small(
    const float* __restrict__ wq, const float* __restrict__ wk,
    const float* __restrict__ wv, const float* __restrict__ wp,
    float* __restrict__ pM, float* __restrict__ pwvp)
{
    int z = blockIdx.z;
    const float* A; const float* B; float* C; int tb;
    if (z < 3) { A = wq + z * DD * DD; B = wk + z * DD * DD; C = pM + z * DD * DD; tb = 1; }
    else       { A = wv + (z - 3) * DD * DD; B = wp + (z - 3) * DD * DD; C = pwvp + (z - 3) * DD * DD; tb = 0; }

    __shared__ float As[16][65];
    __shared__ float Bs[16][65];
    int tid = threadIdx.x;
    int tx = tid & 15, ty = tid >> 4;
    int row0 = blockIdx.y * 64, col0 = blockIdx.x * 64;
    float acc[4][4] = {};

    for (int kt = 0; kt < DD; kt += 16) {
        {   // A tile 64x16, stored transposed
            int r = tid >> 2, c = (tid & 3) * 4;
            float4 v = *(const float4*)(A + (row0 + r) * DD + kt + c);
            As[c + 0][r] = v.x; As[c + 1][r] = v.y; As[c + 2][r] = v.z; As[c + 3][r] = v.w;
        }
        if (tb) { // B^T: Bs[k][c] = B[col0+c, kt+k]
            int c = tid >> 2, k = (tid & 3) * 4;
            float4 v = *(const float4*)(B + (col0 + c) * DD + kt + k);
            Bs[k + 0][c] = v.x; Bs[k + 1][c] = v.y; Bs[k + 2][c] = v.z; Bs[k + 3][c] = v.w;
        } else {  // Bs[k][c] = B[kt+k, col0+c]
            int k = tid >> 4, c = (tid & 15) * 4;
            float4 v = *(const float4*)(B + (kt + k) * DD + col0 + c);
            Bs[k][c + 0] = v.x; Bs[k][c + 1] = v.y; Bs[k][c + 2] = v.z; Bs[k][c + 3] = v.w;
        }
        __syncthreads();
        #pragma unroll
        for (int kk = 0; kk < 16; kk++) {
            float a[4], b[4];
            #pragma unroll
            for (int i = 0; i < 4; i++) { a[i] = As[kk][ty * 4 + i]; b[i] = Bs[kk][tx * 4 + i]; }
            #pragma unroll
            for (int i = 0; i < 4; i++)
                #pragma unroll
                for (int j = 0; j < 4; j++)
                    acc[i][j] += a[i] * b[j];
        }
        __syncthreads();
    }
    #pragma unroll
    for (int i = 0; i < 4; i++)
        #pragma unroll
        for (int j = 0; j < 4; j++)
            C[(row0 + ty * 4 + i) * DD + col0 + tx * 4 + j] = acc[i][j];
}

// ---------------- big GEMM: C[10000,256] = A[10000,256] @ B[256,256] -------
// optional bias + relu epilogue. 128x128x8 tile, 8x8 per thread.
__global__ __launch_bounds__(256, 2) void k_gemm(
    const float* __restrict__ A, const float* __restrict__ B,
    float* __restrict__ C, const float* __restrict__ bias, int relu)
{
    __shared__ float As[8][132];
    __shared__ float Bs[8][132];
    int tid = threadIdx.x;
    int row0 = blockIdx.y * 128, col0 = blockIdx.x * 128;
    int tx = tid & 15, ty = tid >> 4;
    int arow = tid >> 1, acol = (tid & 1) * 4;   // A tile: 128 rows x 8 cols
    int brow = tid >> 5, bcol = (tid & 31) * 4;  // B tile: 8 rows x 128 cols

    float acc[8][8] = {};
    int gr = row0 + arow;

    float4 av = make_float4(0.f, 0.f, 0.f, 0.f);
    if (gr < NN) av = *(const float4*)(A + gr * DD + acol);
    float4 bv = *(const float4*)(B + brow * DD + col0 + bcol);

    for (int kt = 0; kt < DD; kt += 8) {
        As[acol + 0][arow] = av.x; As[acol + 1][arow] = av.y;
        As[acol + 2][arow] = av.z; As[acol + 3][arow] = av.w;
        *(float4*)&Bs[brow][bcol] = bv;
        __syncthreads();
        if (kt + 8 < DD) {
            av = make_float4(0.f, 0.f, 0.f, 0.f);
            if (gr < NN) av = *(const float4*)(A + gr * DD + kt + 8 + acol);
            bv = *(const float4*)(B + (kt + 8 + brow) * DD + col0 + bcol);
        }
        #pragma unroll
        for (int kk = 0; kk < 8; kk++) {
            float a[8], b[8];
            *(float4*)&a[0] = *(const float4*)&As[kk][ty * 8];
            *(float4*)&a[4] = *(const float4*)&As[kk][ty * 8 + 4];
            *(float4*)&b[0] = *(const float4*)&Bs[kk][tx * 8];
            *(float4*)&b[4] = *(const float4*)&Bs[kk][tx * 8 + 4];
            #pragma unroll
            for (int i = 0; i < 8; i++)
                #pragma unroll
                for (int j = 0; j < 8; j++)
                    acc[i][j] += a[i] * b[j];
        }
        __syncthreads();
    }
    #pragma unroll
    for (int i = 0; i < 8; i++) {
        int r = row0 + ty * 8 + i;
        if (r < NN) {
            #pragma unroll
            for (int j = 0; j < 8; j++) {
                float vv = acc[i][j];
                if (bias) vv += bias[col0 + tx * 8 + j];
                if (relu) vv = fmaxf(vv, 0.f);
                C[r * DD + col0 + tx * 8 + j] = vv;
            }
        }
    }
}

// ---------------- per-node online-softmax aggregation ----------------------
// one warp per node; lane owns feats [4*lane,4*lane+4) and [128+4*lane, +4)
// out[n] = relu( (sum_e exp(s_e - m)/Z * u[src_e]) + bp + hin[n] )
// with s_e = (t[n] . hin[src_e]) / 16
__global__ __launch_bounds__(256) void k_edge(
    const float* __restrict__ hin, float* __restrict__ hout,
    const float* __restrict__ bpl)
{
    int gw = (blockIdx.x * blockDim.x + threadIdx.x) >> 5;
    int lane = threadIdx.x & 31;
    if (gw >= NN) return;
    int n = gw;

    const float4* t4 = (const float4*)(g_t + (size_t)n * DD);
    float4 tq0 = t4[lane];
    float4 tq1 = t4[32 + lane];

    float m = -INFINITY, s = 0.f;
    float4 acc0 = make_float4(0.f, 0.f, 0.f, 0.f);
    float4 acc1 = make_float4(0.f, 0.f, 0.f, 0.f);

    int e0 = g_off[n], e1 = g_off[n + 1];
    for (int e = e0; e < e1; e++) {
        int src = g_srcs[e];
        const float4* h4 = (const float4*)(hin + (size_t)src * DD);
        const float4* u4 = (const float4*)(g_u + (size_t)src * DD);
        float4 hk0 = h4[lane];
        float4 hk1 = h4[32 + lane];
        float4 uv0 = u4[lane];
        float4 uv1 = u4[32 + lane];

        float d = tq0.x * hk0.x + tq0.y * hk0.y + tq0.z * hk0.z + tq0.w * hk0.w
                + tq1.x * hk1.x + tq1.y * hk1.y + tq1.z * hk1.z + tq1.w * hk1.w;
        #pragma unroll
        for (int o = 16; o > 0; o >>= 1) d += __shfl_xor_sync(0xffffffffu, d, o);
        d *= 0.0625f;  // 1/sqrt(256)

        float nm = fmaxf(m, d);
        float c = __expf(m - nm);   // 0 when m == -inf
        float w = __expf(d - nm);
        s = s * c + w;
        m = nm;

        acc0.x = acc0.x * c + w * uv0.x; acc0.y = acc0.y * c + w * uv0.y;
        acc0.z = acc0.z * c + w * uv0.z; acc0.w = acc0.w * c + w * uv0.w;
        acc1.x = acc1.x * c + w * uv1.x; acc1.y = acc1.y * c + w * uv1.y;
        acc1.z = acc1.z * c + w * uv1.z; acc1.w = acc1.w * c + w * uv1.w;
    }

    float inv = 1.0f / (s + 1e-9f);
    const float4* hn4 = (const float4*)(hin + (size_t)n * DD);
    float4 hn0 = hn4[lane], hn1 = hn4[32 + lane];
    const float4* b4 = (const float4*)bpl;
    float4 bb0 = b4[lane], bb1 = b4[32 + lane];

    float4 o0, o1;
    o0.x = fmaxf(acc0.x * inv + bb0.x + hn0.x, 0.f);
    o0.y = fmaxf(acc0.y * inv + bb0.y + hn0.y, 0.f);
    o0.z = fmaxf(acc0.z * inv + bb0.z + hn0.z, 0.f);
    o0.w = fmaxf(acc0.w * inv + bb0.w + hn0.w, 0.f);
    o1.x = fmaxf(acc1.x * inv + bb1.x + hn1.x, 0.f);
    o1.y = fmaxf(acc1.y * inv + bb1.y + hn1.y, 0.f);
    o1.z = fmaxf(acc1.z * inv + bb1.z + hn1.z, 0.f);
    o1.w = fmaxf(acc1.w * inv + bb1.w + hn1.w, 0.f);

    float4* out4 = (float4*)(hout + (size_t)n * DD);
    out4[lane] = o0;
    out4[32 + lane] = o1;
}

// ---------------- launch ----------------------------------------------------
extern "C" void kernel_launch(void* const* d_in, const int* in_sizes, int n_in,
                              void* d_out, int out_size)
{
    const float* x    = (const float*)d_in[0];
    const int*   edges= (const int*)  d_in[1];
    const float* w_in = (const float*)d_in[2];
    const float* b_in = (const float*)d_in[3];
    const float* wq   = (const float*)d_in[4];
    const float* wk   = (const float*)d_in[5];
    const float* wv   = (const float*)d_in[6];
    const float* wp   = (const float*)d_in[7];
    const float* bp   = (const float*)d_in[8];
    float* out = (float*)d_out;

    const int* src = edges;
    const int* dst = edges + NE;

    float *phA, *phB, *pt, *pu, *pM, *pwvp;
    cudaGetSymbolAddress((void**)&phA,  g_hA);
    cudaGetSymbolAddress((void**)&phB,  g_hB);
    cudaGetSymbolAddress((void**)&pt,   g_t);
    cudaGetSymbolAddress((void**)&pu,   g_u);
    cudaGetSymbolAddress((void**)&pM,   g_M);
    cudaGetSymbolAddress((void**)&pwvp, g_wvp);

    // CSR build (per call; edges are an input)
    k_init   <<<(NN + 255) / 256, 256>>>();
    k_hist   <<<(NE + 255) / 256, 256>>>(dst);
    k_scan   <<<1, 1024>>>();
    k_scatter<<<(NE + 255) / 256, 256>>>(src, dst);

    // fold weights: M_l = wq_l wk_l^T, wvp_l = wv_l wp_l
    k_small<<<dim3(4, 4, 6), 256>>>(wq, wk, wv, wp, pM, pwvp);

    dim3 gg(2, 79);  // N/128 x ceil(M/128)
    // h0 = relu(x @ w_in + b_in)
    k_gemm<<<gg, 256>>>(x, w_in, phA, b_in, 1);

    float* cur = phA;
    float* nxt = phB;
    for (int l = 0; l < NL; l++) {
        k_gemm<<<gg, 256>>>(cur, pM   + l * DD * DD, pt, nullptr, 0);
        k_gemm<<<gg, 256>>>(cur, pwvp + l * DD * DD, pu, nullptr, 0);
        float* ho = (l == NL - 1) ? out : nxt;
        k_edge<<<(NN * 32 + 255) / 256, 256>>>(cur, ho, bp + l * DD);
        float* tmp = cur; cur = nxt; nxt = tmp;
    }
}

// round 3
// speedup vs baseline: 1.6236x; 1.6236x over previous
#include <cuda_runtime.h>
#include <cuda_bf16.h>
#include <stdint.h>
#include <math.h>

#define NN 10000
#define NE 320000
#define DD 256
#define NL 3

typedef __nv_bfloat16 bf16;
typedef unsigned int uint;

// ---------------- scratch (static device allocations) ----------------------
__device__ float g_hA[NN * DD];
__device__ float g_hB[NN * DD];
__device__ float g_t[NN * DD];            // t = h @ (wq wk^T)
__device__ float g_u[NN * DD];            // u = h @ (wv wp)
__device__ bf16  g_xh[NN * DD], g_xl[NN * DD];
__device__ bf16  g_hh[NN * DD], g_hl[NN * DD];
__device__ bf16  g_winh[DD * DD], g_winl[DD * DD];
__device__ bf16  g_Mh[NL * DD * DD], g_Ml[NL * DD * DD];
__device__ bf16  g_wvph[NL * DD * DD], g_wvpl[NL * DD * DD];
__device__ int   g_deg[NN];
__device__ int   g_off[NN + 1];
__device__ int   g_cur[NN];
__device__ int   g_srcs[NE];

// ---------------- helpers ---------------------------------------------------
__device__ __forceinline__ void f32split(float v, bf16& h, bf16& l) {
    h = __float2bfloat16(v);
    l = __float2bfloat16(v - __bfloat162float(h));
}

__device__ __forceinline__ void ldsm4(uint& r0, uint& r1, uint& r2, uint& r3, uint addr) {
    asm volatile("ldmatrix.sync.aligned.m8n8.x4.shared.b16 {%0,%1,%2,%3}, [%4];"
                 : "=r"(r0), "=r"(r1), "=r"(r2), "=r"(r3) : "r"(addr));
}
__device__ __forceinline__ void ldsm4t(uint& r0, uint& r1, uint& r2, uint& r3, uint addr) {
    asm volatile("ldmatrix.sync.aligned.m8n8.x4.trans.shared.b16 {%0,%1,%2,%3}, [%4];"
                 : "=r"(r0), "=r"(r1), "=r"(r2), "=r"(r3) : "r"(addr));
}
__device__ __forceinline__ void mma_bf16(float* c, const uint* a, uint b0, uint b1) {
    asm volatile("mma.sync.aligned.m16n8k16.row.col.f32.bf16.bf16.f32 "
                 "{%0,%1,%2,%3},{%4,%5,%6,%7},{%8,%9},{%0,%1,%2,%3};"
                 : "+f"(c[0]), "+f"(c[1]), "+f"(c[2]), "+f"(c[3])
                 : "r"(a[0]), "r"(a[1]), "r"(a[2]), "r"(a[3]), "r"(b0), "r"(b1));
}

// ---------------- CSR build -------------------------------------------------
__global__ void k_init() {
    int i = blockIdx.x * blockDim.x + threadIdx.x;
    if (i < NN) { g_deg[i] = 0; g_cur[i] = 0; }
}

__global__ void k_hist(const int* __restrict__ dst) {
    int e = blockIdx.x * blockDim.x + threadIdx.x;
    if (e < NE) atomicAdd(&g_deg[dst[e]], 1);
}

__global__ void k_scan() {
    __shared__ int ws[32];
    int tid = threadIdx.x, lane = tid & 31, wid = tid >> 5;
    int carry = 0;
    for (int base = 0; base < NN; base += 1024) {
        int x = (base + tid < NN) ? g_deg[base + tid] : 0;
        int v = x;
        #pragma unroll
        for (int o = 1; o < 32; o <<= 1) {
            int y = __shfl_up_sync(0xffffffffu, v, o);
            if (lane >= o) v += y;
        }
        if (lane == 31) ws[wid] = v;
        __syncthreads();
        if (tid < 32) {
            int w = ws[tid];
            #pragma unroll
            for (int o = 1; o < 32; o <<= 1) {
                int y = __shfl_up_sync(0xffffffffu, w, o);
                if (tid >= o) w += y;
            }
            ws[tid] = w;
        }
        __syncthreads();
        int add = wid ? ws[wid - 1] : 0;
        if (base + tid < NN) g_off[base + tid] = carry + add + v - x;
        int tot = ws[31];
        __syncthreads();
        carry += tot;
    }
    if (tid == 0) g_off[NN] = carry;
}

__global__ void k_scatter(const int* __restrict__ src, const int* __restrict__ dst) {
    int e = blockIdx.x * blockDim.x + threadIdx.x;
    if (e < NE) {
        int d = dst[e];
        int pos = g_off[d] + atomicAdd(&g_cur[d], 1);
        g_srcs[pos] = src[e];
    }
}

// ---------------- fp32 -> bf16 hi/lo conversion ------------------------------
__global__ void k_cvt(const float* __restrict__ in, bf16* __restrict__ h,
                      bf16* __restrict__ l, int n) {
    int i = blockIdx.x * blockDim.x + threadIdx.x;
    if (i < n) {
        bf16 hh, ll;
        f32split(in[i], hh, ll);
        h[i] = hh; l[i] = ll;
    }
}

// ---------------- tiny 256x256x256 GEMMs (weight folding) -> bf16 hi/lo -----
__global__ __launch_bounds__(256) void k_small(
    const float* __restrict__ wq, const float* __restrict__ wk,
    const float* __restrict__ wv, const float* __restrict__ wp,
    bf16* __restrict__ pMh, bf16* __restrict__ pMl,
    bf16* __restrict__ pWh, bf16* __restrict__ pWl)
{
    int z = blockIdx.z;
    const float* A; const float* B; bf16* Ch; bf16* Cl; int tb;
    if (z < 3) { A = wq + z * DD * DD; B = wk + z * DD * DD;
                 Ch = pMh + z * DD * DD; Cl = pMl + z * DD * DD; tb = 1; }
    else       { A = wv + (z - 3) * DD * DD; B = wp + (z - 3) * DD * DD;
                 Ch = pWh + (z - 3) * DD * DD; Cl = pWl + (z - 3) * DD * DD; tb = 0; }

    __shared__ float As[16][65];
    __shared__ float Bs[16][65];
    int tid = threadIdx.x;
    int tx = tid & 15, ty = tid >> 4;
    int row0 = blockIdx.y * 64, col0 = blockIdx.x * 64;
    float acc[4][4] = {};

    for (int kt = 0; kt < DD; kt += 16) {
        {
            int r = tid >> 2, c = (tid & 3) * 4;
            float4 v = *(const float4*)(A + (row0 + r) * DD + kt + c);
            As[c + 0][r] = v.x; As[c + 1][r] = v.y; As[c + 2][r] = v.z; As[c + 3][r] = v.w;
        }
        if (tb) {
            int c = tid >> 2, k = (tid & 3) * 4;
            float4 v = *(const float4*)(B + (col0 + c) * DD + kt + k);
            Bs[k + 0][c] = v.x; Bs[k + 1][c] = v.y; Bs[k + 2][c] = v.z; Bs[k + 3][c] = v.w;
        } else {
            int k = tid >> 4, c = (tid & 15) * 4;
            float4 v = *(const float4*)(B + (kt + k) * DD + col0 + c);
            Bs[k][c + 0] = v.x; Bs[k][c + 1] = v.y; Bs[k][c + 2] = v.z; Bs[k][c + 3] = v.w;
        }
        __syncthreads();
        #pragma unroll
        for (int kk = 0; kk < 16; kk++) {
            float a[4], b[4];
            #pragma unroll
            for (int i = 0; i < 4; i++) { a[i] = As[kk][ty * 4 + i]; b[i] = Bs[kk][tx * 4 + i]; }
            #pragma unroll
            for (int i = 0; i < 4; i++)
                #pragma unroll
                for (int j = 0; j < 4; j++)
                    acc[i][j] += a[i] * b[j];
        }
        __syncthreads();
    }
    #pragma unroll
    for (int i = 0; i < 4; i++)
        #pragma unroll
        for (int j = 0; j < 4; j++) {
            bf16 h, l;
            f32split(acc[i][j], h, l);
            int idx = (row0 + ty * 4 + i) * DD + col0 + tx * 4 + j;
            Ch[idx] = h; Cl[idx] = l;
        }
}

// ---------------- tensor-core GEMM: C[10000,256] = A @ B ---------------------
// A given as (Ah+Al), B as (Bh+Bl) bf16; computes AhBh + AhBl + AlBh in fp32.
// CTA tile 128x128, 8 warps of 64x32, k-step 32, register-staged double buffer.
__global__ __launch_bounds__(256, 1) void k_mma(
    const bf16* __restrict__ Ah, const bf16* __restrict__ Al,
    const bf16* __restrict__ Bh, const bf16* __restrict__ Bl,
    float* __restrict__ C, const float* __restrict__ bias, int relu,
    bf16* __restrict__ Chi, bf16* __restrict__ Clo)
{
    __shared__ __align__(16) bf16 sAh[128][40], sAl[128][40];
    __shared__ __align__(16) bf16 sBh[32][136], sBl[32][136];

    int tid = threadIdx.x;
    int lane = tid & 31, warp = tid >> 5;
    int wm = warp & 1, wn = warp >> 1;        // 2 M-warps x 4 N-warps
    int row0 = blockIdx.y * 128, col0 = blockIdx.x * 128;

    // gmem->smem chunk assignment (16B chunks)
    int ar0 = tid >> 2,         ac0 = (tid & 3) * 8;
    int ar1 = (tid + 256) >> 2, ac1 = (tid & 3) * 8;
    int br0 = tid >> 4,         bc0 = (tid & 15) * 8;
    int br1 = (tid + 256) >> 4, bc1 = (tid & 15) * 8;

    uint4 rAh0, rAh1, rAl0, rAl1, rBh0, rBh1, rBl0, rBl1;
    const uint4 z4 = make_uint4(0u, 0u, 0u, 0u);

    auto loadA = [&](int kt) {
        int r0g = row0 + ar0, r1g = row0 + ar1;
        rAh0 = (r0g < NN) ? *(const uint4*)(Ah + (size_t)r0g * DD + kt + ac0) : z4;
        rAl0 = (r0g < NN) ? *(const uint4*)(Al + (size_t)r0g * DD + kt + ac0) : z4;
        rAh1 = (r1g < NN) ? *(const uint4*)(Ah + (size_t)r1g * DD + kt + ac1) : z4;
        rAl1 = (r1g < NN) ? *(const uint4*)(Al + (size_t)r1g * DD + kt + ac1) : z4;
        rBh0 = *(const uint4*)(Bh + (size_t)(kt + br0) * DD + col0 + bc0);
        rBh1 = *(const uint4*)(Bh + (size_t)(kt + br1) * DD + col0 + bc1);
        rBl0 = *(const uint4*)(Bl + (size_t)(kt + br0) * DD + col0 + bc0);
        rBl1 = *(const uint4*)(Bl + (size_t)(kt + br1) * DD + col0 + bc1);
    };
    auto storeS = [&]() {
        *(uint4*)&sAh[ar0][ac0] = rAh0; *(uint4*)&sAl[ar0][ac0] = rAl0;
        *(uint4*)&sAh[ar1][ac1] = rAh1; *(uint4*)&sAl[ar1][ac1] = rAl1;
        *(uint4*)&sBh[br0][bc0] = rBh0; *(uint4*)&sBh[br1][bc1] = rBh1;
        *(uint4*)&sBl[br0][bc0] = rBl0; *(uint4*)&sBl[br1][bc1] = rBl1;
    };

    uint aAh = (uint)__cvta_generic_to_shared(&sAh[0][0]);
    uint aAl = (uint)__cvta_generic_to_shared(&sAl[0][0]);
    uint aBh = (uint)__cvta_generic_to_shared(&sBh[0][0]);
    uint aBl = (uint)__cvta_generic_to_shared(&sBl[0][0]);

    float acc[4][4][4] = {};

    loadA(0);
    storeS();
    __syncthreads();

    for (int kt = 0; kt < DD; kt += 32) {
        bool more = (kt + 32) < DD;
        if (more) loadA(kt + 32);

        #pragma unroll
        for (int ks = 0; ks < 32; ks += 16) {
            int arow = lane & 15;
            int kcol = ks + ((lane >> 4) << 3);
            uint ah[4][4], al[4][4];
            #pragma unroll
            for (int mi = 0; mi < 4; mi++) {
                uint off = (uint)((wm * 64 + mi * 16 + arow) * 40 + kcol) * 2;
                ldsm4(ah[mi][0], ah[mi][1], ah[mi][2], ah[mi][3], aAh + off);
                ldsm4(al[mi][0], al[mi][1], al[mi][2], al[mi][3], aAl + off);
            }
            uint bhf[2][4], blf[2][4];
            int brow = ks + (lane & 15);
            #pragma unroll
            for (int ng = 0; ng < 2; ng++) {
                int bcol = wn * 32 + ng * 16 + ((lane >> 4) << 3);
                uint off = (uint)(brow * 136 + bcol) * 2;
                ldsm4t(bhf[ng][0], bhf[ng][1], bhf[ng][2], bhf[ng][3], aBh + off);
                ldsm4t(blf[ng][0], blf[ng][1], blf[ng][2], blf[ng][3], aBl + off);
            }
            #pragma unroll
            for (int mi = 0; mi < 4; mi++)
                #pragma unroll
                for (int ng = 0; ng < 2; ng++) {
                    mma_bf16(acc[mi][ng * 2],     ah[mi], bhf[ng][0], bhf[ng][1]);
                    mma_bf16(acc[mi][ng * 2 + 1], ah[mi], bhf[ng][2], bhf[ng][3]);
                    mma_bf16(acc[mi][ng * 2],     ah[mi], blf[ng][0], blf[ng][1]);
                    mma_bf16(acc[mi][ng * 2 + 1], ah[mi], blf[ng][2], blf[ng][3]);
                    mma_bf16(acc[mi][ng * 2],     al[mi], bhf[ng][0], bhf[ng][1]);
                    mma_bf16(acc[mi][ng * 2 + 1], al[mi], bhf[ng][2], bhf[ng][3]);
                }
        }
        __syncthreads();
        if (more) { storeS(); __syncthreads(); }
    }

    // epilogue
    int grp = lane >> 2, q = lane & 3;
    #pragma unroll
    for (int mi = 0; mi < 4; mi++) {
        int rb = row0 + wm * 64 + mi * 16 + grp;
        #pragma unroll
        for (int nj = 0; nj < 4; nj++) {
            int cb = col0 + wn * 32 + nj * 8 + q * 2;
            float v0 = acc[mi][nj][0], v1 = acc[mi][nj][1];
            float v2 = acc[mi][nj][2], v3 = acc[mi][nj][3];
            if (bias) {
                float b0 = bias[cb], b1 = bias[cb + 1];
                v0 += b0; v1 += b1; v2 += b0; v3 += b1;
            }
            if (relu) {
                v0 = fmaxf(v0, 0.f); v1 = fmaxf(v1, 0.f);
                v2 = fmaxf(v2, 0.f); v3 = fmaxf(v3, 0.f);
            }
            if (rb < NN) {
                size_t o = (size_t)rb * DD + cb;
                C[o] = v0; C[o + 1] = v1;
                if (Chi) {
                    bf16 h0, l0, h1, l1;
                    f32split(v0, h0, l0); f32split(v1, h1, l1);
                    Chi[o] = h0; Chi[o + 1] = h1;
                    Clo[o] = l0; Clo[o + 1] = l1;
                }
            }
            if (rb + 8 < NN) {
                size_t o = (size_t)(rb + 8) * DD + cb;
                C[o] = v2; C[o + 1] = v3;
                if (Chi) {
                    bf16 h2, l2, h3, l3;
                    f32split(v2, h2, l2); f32split(v3, h3, l3);
                    Chi[o] = h2; Chi[o + 1] = h3;
                    Clo[o] = l2; Clo[o + 1] = l3;
                }
            }
        }
    }
}

// ---------------- per-node online-softmax aggregation ------------------------
__global__ __launch_bounds__(256) void k_edge(
    const float* __restrict__ hin, float* __restrict__ hout,
    const float* __restrict__ bpl, bf16* __restrict__ hh, bf16* __restrict__ hl)
{
    int gw = (blockIdx.x * blockDim.x + threadIdx.x) >> 5;
    int lane = threadIdx.x & 31;
    if (gw >= NN) return;
    int n = gw;

    const float4* t4 = (const float4*)(g_t + (size_t)n * DD);
    float4 tq0 = t4[lane];
    float4 tq1 = t4[32 + lane];

    float m = -INFINITY, s = 0.f;
    float4 acc0 = make_float4(0.f, 0.f, 0.f, 0.f);
    float4 acc1 = make_float4(0.f, 0.f, 0.f, 0.f);

    int e0 = g_off[n], e1 = g_off[n + 1];
    for (int e = e0; e < e1; e++) {
        int src = g_srcs[e];
        const float4* h4 = (const float4*)(hin + (size_t)src * DD);
        const float4* u4 = (const float4*)(g_u + (size_t)src * DD);
        float4 hk0 = h4[lane];
        float4 hk1 = h4[32 + lane];
        float4 uv0 = u4[lane];
        float4 uv1 = u4[32 + lane];

        float d = tq0.x * hk0.x + tq0.y * hk0.y + tq0.z * hk0.z + tq0.w * hk0.w
                + tq1.x * hk1.x + tq1.y * hk1.y + tq1.z * hk1.z + tq1.w * hk1.w;
        #pragma unroll
        for (int o = 16; o > 0; o >>= 1) d += __shfl_xor_sync(0xffffffffu, d, o);
        d *= 0.0625f;

        float nm = fmaxf(m, d);
        float c = __expf(m - nm);
        float w = __expf(d - nm);
        s = s * c + w;
        m = nm;

        acc0.x = acc0.x * c + w * uv0.x; acc0.y = acc0.y * c + w * uv0.y;
        acc0.z = acc0.z * c + w * uv0.z; acc0.w = acc0.w * c + w * uv0.w;
        acc1.x = acc1.x * c + w * uv1.x; acc1.y = acc1.y * c + w * uv1.y;
        acc1.z = acc1.z * c + w * uv1.z; acc1.w = acc1.w * c + w * uv1.w;
    }

    float inv = 1.0f / (s + 1e-9f);
    const float4* hn4 = (const float4*)(hin + (size_t)n * DD);
    float4 hn0 = hn4[lane], hn1 = hn4[32 + lane];
    const float4* b4 = (const float4*)bpl;
    float4 bb0 = b4[lane], bb1 = b4[32 + lane];

    float4 o0, o1;
    o0.x = fmaxf(acc0.x * inv + bb0.x + hn0.x, 0.f);
    o0.y = fmaxf(acc0.y * inv + bb0.y + hn0.y, 0.f);
    o0.z = fmaxf(acc0.z * inv + bb0.z + hn0.z, 0.f);
    o0.w = fmaxf(acc0.w * inv + bb0.w + hn0.w, 0.f);
    o1.x = fmaxf(acc1.x * inv + bb1.x + hn1.x, 0.f);
    o1.y = fmaxf(acc1.y * inv + bb1.y + hn1.y, 0.f);
    o1.z = fmaxf(acc1.z * inv + bb1.z + hn1.z, 0.f);
    o1.w = fmaxf(acc1.w * inv + bb1.w + hn1.w, 0.f);

    float4* out4 = (float4*)(hout + (size_t)n * DD);
    out4[lane] = o0;
    out4[32 + lane] = o1;

    if (hh) {
        __nv_bfloat162* hh2 = (__nv_bfloat162*)(hh + (size_t)n * DD);
        __nv_bfloat162* hl2 = (__nv_bfloat162*)(hl + (size_t)n * DD);
        bf16 a, b, c, d2, la, lb, lc, ld;
        f32split(o0.x, a, la); f32split(o0.y, b, lb);
        f32split(o0.z, c, lc); f32split(o0.w, d2, ld);
        hh2[2 * lane]     = __halves2bfloat162(a, b);
        hh2[2 * lane + 1] = __halves2bfloat162(c, d2);
        hl2[2 * lane]     = __halves2bfloat162(la, lb);
        hl2[2 * lane + 1] = __halves2bfloat162(lc, ld);
        f32split(o1.x, a, la); f32split(o1.y, b, lb);
        f32split(o1.z, c, lc); f32split(o1.w, d2, ld);
        hh2[64 + 2 * lane]     = __halves2bfloat162(a, b);
        hh2[64 + 2 * lane + 1] = __halves2bfloat162(c, d2);
        hl2[64 + 2 * lane]     = __halves2bfloat162(la, lb);
        hl2[64 + 2 * lane + 1] = __halves2bfloat162(lc, ld);
    }
}

// ---------------- launch ------------------------------------------------------
extern "C" void kernel_launch(void* const* d_in, const int* in_sizes, int n_in,
                              void* d_out, int out_size)
{
    const float* x    = (const float*)d_in[0];
    const int*   edges= (const int*)  d_in[1];
    const float* w_in = (const float*)d_in[2];
    const float* b_in = (const float*)d_in[3];
    const float* wq   = (const float*)d_in[4];
    const float* wk   = (const float*)d_in[5];
    const float* wv   = (const float*)d_in[6];
    const float* wp   = (const float*)d_in[7];
    const float* bp   = (const float*)d_in[8];
    float* out = (float*)d_out;

    const int* src = edges;
    const int* dst = edges + NE;

    float *phA, *phB, *pt, *pu;
    bf16 *pxh, *pxl, *phh, *phl, *pwinh, *pwinl, *pMh, *pMl, *pWh, *pWl;
    cudaGetSymbolAddress((void**)&phA,   g_hA);
    cudaGetSymbolAddress((void**)&phB,   g_hB);
    cudaGetSymbolAddress((void**)&pt,    g_t);
    cudaGetSymbolAddress((void**)&pu,    g_u);
    cudaGetSymbolAddress((void**)&pxh,   g_xh);
    cudaGetSymbolAddress((void**)&pxl,   g_xl);
    cudaGetSymbolAddress((void**)&phh,   g_hh);
    cudaGetSymbolAddress((void**)&phl,   g_hl);
    cudaGetSymbolAddress((void**)&pwinh, g_winh);
    cudaGetSymbolAddress((void**)&pwinl, g_winl);
    cudaGetSymbolAddress((void**)&pMh,   g_Mh);
    cudaGetSymbolAddress((void**)&pMl,   g_Ml);
    cudaGetSymbolAddress((void**)&pWh,   g_wvph);
    cudaGetSymbolAddress((void**)&pWl,   g_wvpl);

    // CSR build
    k_init   <<<(NN + 255) / 256, 256>>>();
    k_hist   <<<(NE + 255) / 256, 256>>>(dst);
    k_scan   <<<1, 1024>>>();
    k_scatter<<<(NE + 255) / 256, 256>>>(src, dst);

    // conversions + weight folding
    k_cvt<<<(NN * DD + 255) / 256, 256>>>(x, pxh, pxl, NN * DD);
    k_cvt<<<(DD * DD + 255) / 256, 256>>>(w_in, pwinh, pwinl, DD * DD);
    k_small<<<dim3(4, 4, 6), 256>>>(wq, wk, wv, wp, pMh, pMl, pWh, pWl);

    dim3 gg(2, 79);
    // h0 = relu(x @ w_in + b_in)  (fp32 out + bf16 hi/lo out)
    k_mma<<<gg, 256>>>(pxh, pxl, pwinh, pwinl, phA, b_in, 1, phh, phl);

    float* cur = phA;
    float* nxt = phB;
    for (int l = 0; l < NL; l++) {
        k_mma<<<gg, 256>>>(phh, phl, pMh + l * DD * DD, pMl + l * DD * DD,
                           pt, nullptr, 0, nullptr, nullptr);
        k_mma<<<gg, 256>>>(phh, phl, pWh + l * DD * DD, pWl + l * DD * DD,
                           pu, nullptr, 0, nullptr, nullptr);
        float* ho = (l == NL - 1) ? out : nxt;
        bf16* oh = (l == NL - 1) ? nullptr : phh;
        bf16* ol = (l == NL - 1) ? nullptr : phl;
        k_edge<<<(NN * 32 + 255) / 256, 256>>>(cur, ho, bp + l * DD, oh, ol);
        float* tmp = cur; cur = nxt; nxt = tmp;
    }
}

// round 4
// speedup vs baseline: 1.8661x; 1.1493x over previous
#include <cuda_runtime.h>
#include <cuda_bf16.h>
#include <stdint.h>
#include <math.h>

#define NN 10000
#define NE 320000
#define DD 256
#define NL 3

typedef __nv_bfloat16 bf16;
typedef unsigned int uint;

// ---------------- scratch -----------------------------------------------------
__device__ float g_hA[NN * DD];
__device__ float g_hB[NN * DD];
__device__ float g_t[NN * DD];
__device__ bf16  g_ub[NN * DD];                         // u in bf16
__device__ bf16  g_xh[NN * DD], g_xl[NN * DD];
__device__ bf16  g_hhA[NN * DD], g_hlA[NN * DD];        // bf16 h ping
__device__ bf16  g_hhB[NN * DD], g_hlB[NN * DD];        // bf16 h pong
__device__ bf16  g_winh[DD * DD], g_winl[DD * DD];
__device__ bf16  g_Mh[NL * DD * DD], g_Ml[NL * DD * DD];
__device__ bf16  g_wvph[NL * DD * DD], g_wvpl[NL * DD * DD];
__device__ int   g_deg[NN];
__device__ int   g_off[NN + 1];
__device__ int   g_cur[NN];
__device__ int   g_srcs[NE];

// ---------------- helpers -----------------------------------------------------
__device__ __forceinline__ void f32split(float v, bf16& h, bf16& l) {
    h = __float2bfloat16(v);
    l = __float2bfloat16(v - __bfloat162float(h));
}
__device__ __forceinline__ void ldsm4(uint& r0, uint& r1, uint& r2, uint& r3, uint addr) {
    asm volatile("ldmatrix.sync.aligned.m8n8.x4.shared.b16 {%0,%1,%2,%3}, [%4];"
                 : "=r"(r0), "=r"(r1), "=r"(r2), "=r"(r3) : "r"(addr));
}
__device__ __forceinline__ void ldsm4t(uint& r0, uint& r1, uint& r2, uint& r3, uint addr) {
    asm volatile("ldmatrix.sync.aligned.m8n8.x4.trans.shared.b16 {%0,%1,%2,%3}, [%4];"
                 : "=r"(r0), "=r"(r1), "=r"(r2), "=r"(r3) : "r"(addr));
}
__device__ __forceinline__ void mma_bf16(float* c, const uint* a, uint b0, uint b1) {
    asm volatile("mma.sync.aligned.m16n8k16.row.col.f32.bf16.bf16.f32 "
                 "{%0,%1,%2,%3},{%4,%5,%6,%7},{%8,%9},{%0,%1,%2,%3};"
                 : "+f"(c[0]), "+f"(c[1]), "+f"(c[2]), "+f"(c[3])
                 : "r"(a[0]), "r"(a[1]), "r"(a[2]), "r"(a[3]), "r"(b0), "r"(b1));
}
__device__ __forceinline__ void cp16(uint dst, const void* src) {
    asm volatile("cp.async.cg.shared.global [%0], [%1], 16;" :: "r"(dst), "l"(src));
}
__device__ __forceinline__ void cp16z(uint dst, const void* src, uint sz) {
    asm volatile("cp.async.cg.shared.global [%0], [%1], 16, %2;" :: "r"(dst), "l"(src), "r"(sz));
}
__device__ __forceinline__ void cp_commit() { asm volatile("cp.async.commit_group;"); }

// ---------------- CSR build ----------------------------------------------------
__global__ void k_init() {
    int i = blockIdx.x * blockDim.x + threadIdx.x;
    if (i < NN) { g_deg[i] = 0; g_cur[i] = 0; }
}
__global__ void k_hist(const int* __restrict__ dst) {
    int e = blockIdx.x * blockDim.x + threadIdx.x;
    if (e < NE) atomicAdd(&g_deg[dst[e]], 1);
}
__global__ void k_scan() {
    __shared__ int ws[32];
    int tid = threadIdx.x, lane = tid & 31, wid = tid >> 5;
    int carry = 0;
    for (int base = 0; base < NN; base += 1024) {
        int x = (base + tid < NN) ? g_deg[base + tid] : 0;
        int v = x;
        #pragma unroll
        for (int o = 1; o < 32; o <<= 1) {
            int y = __shfl_up_sync(0xffffffffu, v, o);
            if (lane >= o) v += y;
        }
        if (lane == 31) ws[wid] = v;
        __syncthreads();
        if (tid < 32) {
            int w = ws[tid];
            #pragma unroll
            for (int o = 1; o < 32; o <<= 1) {
                int y = __shfl_up_sync(0xffffffffu, w, o);
                if (tid >= o) w += y;
            }
            ws[tid] = w;
        }
        __syncthreads();
        int add = wid ? ws[wid - 1] : 0;
        if (base + tid < NN) g_off[base + tid] = carry + add + v - x;
        int tot = ws[31];
        __syncthreads();
        carry += tot;
    }
    if (tid == 0) g_off[NN] = carry;
}
__global__ void k_scatter(const int* __restrict__ src, const int* __restrict__ dst) {
    int e = blockIdx.x * blockDim.x + threadIdx.x;
    if (e < NE) {
        int d = dst[e];
        int pos = g_off[d] + atomicAdd(&g_cur[d], 1);
        g_srcs[pos] = src[e];
    }
}

// ---------------- fp32 -> bf16 hi/lo -------------------------------------------
__global__ void k_cvt(const float* __restrict__ in, bf16* __restrict__ h,
                      bf16* __restrict__ l, int n) {
    int i = blockIdx.x * blockDim.x + threadIdx.x;
    if (i < n) {
        bf16 hh, ll;
        f32split(in[i], hh, ll);
        h[i] = hh; l[i] = ll;
    }
}

// ---------------- weight folding ------------------------------------------------
__global__ __launch_bounds__(256) void k_small(
    const float* __restrict__ wq, const float* __restrict__ wk,
    const float* __restrict__ wv, const float* __restrict__ wp,
    bf16* __restrict__ pMh, bf16* __restrict__ pMl,
    bf16* __restrict__ pWh, bf16* __restrict__ pWl)
{
    int z = blockIdx.z;
    const float* A; const float* B; bf16* Ch; bf16* Cl; int tb;
    if (z < 3) { A = wq + z * DD * DD; B = wk + z * DD * DD;
                 Ch = pMh + z * DD * DD; Cl = pMl + z * DD * DD; tb = 1; }
    else       { A = wv + (z - 3) * DD * DD; B = wp + (z - 3) * DD * DD;
                 Ch = pWh + (z - 3) * DD * DD; Cl = pWl + (z - 3) * DD * DD; tb = 0; }

    __shared__ float As[16][65];
    __shared__ float Bs[16][65];
    int tid = threadIdx.x;
    int tx = tid & 15, ty = tid >> 4;
    int row0 = blockIdx.y * 64, col0 = blockIdx.x * 64;
    float acc[4][4] = {};

    for (int kt = 0; kt < DD; kt += 16) {
        {
            int r = tid >> 2, c = (tid & 3) * 4;
            float4 v = *(const float4*)(A + (row0 + r) * DD + kt + c);
            As[c + 0][r] = v.x; As[c + 1][r] = v.y; As[c + 2][r] = v.z; As[c + 3][r] = v.w;
        }
        if (tb) {
            int c = tid >> 2, k = (tid & 3) * 4;
            float4 v = *(const float4*)(B + (col0 + c) * DD + kt + k);
            Bs[k + 0][c] = v.x; Bs[k + 1][c] = v.y; Bs[k + 2][c] = v.z; Bs[k + 3][c] = v.w;
        } else {
            int k = tid >> 4, c = (tid & 15) * 4;
            float4 v = *(const float4*)(B + (kt + k) * DD + col0 + c);
            Bs[k][c + 0] = v.x; Bs[k][c + 1] = v.y; Bs[k][c + 2] = v.z; Bs[k][c + 3] = v.w;
        }
        __syncthreads();
        #pragma unroll
        for (int kk = 0; kk < 16; kk++) {
            float a[4], b[4];
            #pragma unroll
            for (int i = 0; i < 4; i++) { a[i] = As[kk][ty * 4 + i]; b[i] = Bs[kk][tx * 4 + i]; }
            #pragma unroll
            for (int i = 0; i < 4; i++)
                #pragma unroll
                for (int j = 0; j < 4; j++)
                    acc[i][j] += a[i] * b[j];
        }
        __syncthreads();
    }
    #pragma unroll
    for (int i = 0; i < 4; i++)
        #pragma unroll
        for (int j = 0; j < 4; j++) {
            bf16 h, l;
            f32split(acc[i][j], h, l);
            int idx = (row0 + ty * 4 + i) * DD + col0 + tx * 4 + j;
            Ch[idx] = h; Cl[idx] = l;
        }
}

// ---------------- tensor-core GEMM with cp.async 3-stage pipeline --------------
// stage layout in dyn smem (bf16 elems): Ah@0 (128x40), Al@5120, Bh@10240 (32x136), Bl@14592
#define ST_ELEMS 18944
#define A_PITCH 40
#define B_PITCH 136

template<int USE_BL>
__global__ __launch_bounds__(256, 1) void k_mma(
    const bf16* __restrict__ Ah, const bf16* __restrict__ Al,
    const bf16* __restrict__ Bh, const bf16* __restrict__ Bl,
    float* __restrict__ C, const float* __restrict__ bias, int relu,
    bf16* __restrict__ Chi, bf16* __restrict__ Clo)
{
    extern __shared__ __align__(16) bf16 smem[];
    int tid = threadIdx.x;
    int lane = tid & 31, warp = tid >> 5;
    int wm = warp & 1, wn = warp >> 1;
    int row0 = blockIdx.y * 128, col0 = blockIdx.x * 128;

    uint sbase = (uint)__cvta_generic_to_shared(smem);

    // per-thread cp.async chunk coords
    // A: 512 chunks of 16B per (hi/lo): row=c>>2, col=(c&3)*8
    int a_r0 = tid >> 2,        a_c0 = (tid & 3) * 8;
    int a_r1 = (tid + 256) >> 2;
    // B: 512 chunks: row=c>>4, col=(c&15)*8
    int b_r0 = tid >> 4,        b_c0 = (tid & 15) * 8;
    int b_r1 = (tid + 256) >> 4;

    int ga0 = row0 + a_r0, ga1 = row0 + a_r1;
    uint sz0 = (ga0 < NN) ? 16u : 0u;
    uint sz1 = (ga1 < NN) ? 16u : 0u;
    int ca0 = (ga0 < NN) ? ga0 : 0;
    int ca1 = (ga1 < NN) ? ga1 : 0;

    auto issue = [&](int st, int kt) {
        uint base = sbase + (uint)(st * ST_ELEMS) * 2u;
        uint dA0 = base + (uint)(a_r0 * A_PITCH + a_c0) * 2u;
        uint dA1 = base + (uint)(a_r1 * A_PITCH + a_c0) * 2u;
        cp16z(dA0,            Ah + (size_t)ca0 * DD + kt + a_c0, sz0);
        cp16z(dA1,            Ah + (size_t)ca1 * DD + kt + a_c0, sz1);
        cp16z(dA0 + 5120u*2u, Al + (size_t)ca0 * DD + kt + a_c0, sz0);
        cp16z(dA1 + 5120u*2u, Al + (size_t)ca1 * DD + kt + a_c0, sz1);
        uint dB0 = base + (10240u + (uint)(b_r0 * B_PITCH + b_c0)) * 2u;
        uint dB1 = base + (10240u + (uint)(b_r1 * B_PITCH + b_c0)) * 2u;
        cp16(dB0, Bh + (size_t)(kt + b_r0) * DD + col0 + b_c0);
        cp16(dB1, Bh + (size_t)(kt + b_r1) * DD + col0 + b_c0);
        if (USE_BL) {
            cp16(dB0 + (14592u-10240u)*2u, Bl + (size_t)(kt + b_r0) * DD + col0 + b_c0);
            cp16(dB1 + (14592u-10240u)*2u, Bl + (size_t)(kt + b_r1) * DD + col0 + b_c0);
        }
    };

    float acc[4][4][4] = {};

    issue(0, 0);   cp_commit();
    issue(1, 32);  cp_commit();

    #pragma unroll
    for (int i = 0; i < 8; i++) {
        if (i < 7) asm volatile("cp.async.wait_group 1;");
        else       asm volatile("cp.async.wait_group 0;");
        __syncthreads();
        if (i < 6) { issue((i + 2) % 3, (i + 2) * 32); cp_commit(); }

        int st = i % 3;
        uint base = sbase + (uint)(st * ST_ELEMS) * 2u;
        uint aAh = base;
        uint aAl = base + 5120u * 2u;
        uint aBh = base + 10240u * 2u;
        uint aBl = base + 14592u * 2u;

        #pragma unroll
        for (int ks = 0; ks < 32; ks += 16) {
            int arow = lane & 15;
            int kcol = ks + ((lane >> 4) << 3);
            uint ah[4][4], al[4][4];
            #pragma unroll
            for (int mi = 0; mi < 4; mi++) {
                uint off = (uint)((wm * 64 + mi * 16 + arow) * A_PITCH + kcol) * 2u;
                ldsm4(ah[mi][0], ah[mi][1], ah[mi][2], ah[mi][3], aAh + off);
                ldsm4(al[mi][0], al[mi][1], al[mi][2], al[mi][3], aAl + off);
            }
            uint bhf[2][4], blf[2][4];
            int brow = ks + (lane & 15);
            #pragma unroll
            for (int ng = 0; ng < 2; ng++) {
                int bcol = wn * 32 + ng * 16 + ((lane >> 4) << 3);
                uint off = (uint)(brow * B_PITCH + bcol) * 2u;
                ldsm4t(bhf[ng][0], bhf[ng][1], bhf[ng][2], bhf[ng][3], aBh + off);
                if (USE_BL) ldsm4t(blf[ng][0], blf[ng][1], blf[ng][2], blf[ng][3], aBl + off);
            }
            #pragma unroll
            for (int mi = 0; mi < 4; mi++)
                #pragma unroll
                for (int ng = 0; ng < 2; ng++) {
                    mma_bf16(acc[mi][ng * 2],     ah[mi], bhf[ng][0], bhf[ng][1]);
                    mma_bf16(acc[mi][ng * 2 + 1], ah[mi], bhf[ng][2], bhf[ng][3]);
                    mma_bf16(acc[mi][ng * 2],     al[mi], bhf[ng][0], bhf[ng][1]);
                    mma_bf16(acc[mi][ng * 2 + 1], al[mi], bhf[ng][2], bhf[ng][3]);
                    if (USE_BL) {
                        mma_bf16(acc[mi][ng * 2],     ah[mi], blf[ng][0], blf[ng][1]);
                        mma_bf16(acc[mi][ng * 2 + 1], ah[mi], blf[ng][2], blf[ng][3]);
                    }
                }
        }
        __syncthreads();
    }

    // epilogue
    int grp = lane >> 2, q = lane & 3;
    #pragma unroll
    for (int mi = 0; mi < 4; mi++) {
        int rb = row0 + wm * 64 + mi * 16 + grp;
        #pragma unroll
        for (int nj = 0; nj < 4; nj++) {
            int cb = col0 + wn * 32 + nj * 8 + q * 2;
            float v0 = acc[mi][nj][0], v1 = acc[mi][nj][1];
            float v2 = acc[mi][nj][2], v3 = acc[mi][nj][3];
            if (bias) {
                float b0 = bias[cb], b1 = bias[cb + 1];
                v0 += b0; v1 += b1; v2 += b0; v3 += b1;
            }
            if (relu) {
                v0 = fmaxf(v0, 0.f); v1 = fmaxf(v1, 0.f);
                v2 = fmaxf(v2, 0.f); v3 = fmaxf(v3, 0.f);
            }
            if (rb < NN) {
                size_t o = (size_t)rb * DD + cb;
                if (C) { C[o] = v0; C[o + 1] = v1; }
                if (Chi) {
                    if (Clo) {
                        bf16 h0, l0, h1, l1;
                        f32split(v0, h0, l0); f32split(v1, h1, l1);
                        Chi[o] = h0; Chi[o + 1] = h1;
                        Clo[o] = l0; Clo[o + 1] = l1;
                    } else {
                        Chi[o] = __float2bfloat16(v0); Chi[o + 1] = __float2bfloat16(v1);
                    }
                }
            }
            if (rb + 8 < NN) {
                size_t o = (size_t)(rb + 8) * DD + cb;
                if (C) { C[o] = v2; C[o + 1] = v3; }
                if (Chi) {
                    if (Clo) {
                        bf16 h2, l2, h3, l3;
                        f32split(v2, h2, l2); f32split(v3, h3, l3);
                        Chi[o] = h2; Chi[o + 1] = h3;
                        Clo[o] = l2; Clo[o + 1] = l3;
                    } else {
                        Chi[o] = __float2bfloat16(v2); Chi[o + 1] = __float2bfloat16(v3);
                    }
                }
            }
        }
    }
}

// ---------------- per-node online-softmax aggregation (bf16 gathers) -----------
__global__ __launch_bounds__(256) void k_edge(
    const float* __restrict__ hin, float* __restrict__ hout,
    const float* __restrict__ bpl,
    const bf16* __restrict__ hhin,
    bf16* __restrict__ hhout, bf16* __restrict__ hlout)
{
    int gw = (blockIdx.x * blockDim.x + threadIdx.x) >> 5;
    int lane = threadIdx.x & 31;
    if (gw >= NN) return;
    int n = gw;
    int c0 = lane * 8;

    float t8[8];
    *(float4*)&t8[0] = *(const float4*)(g_t + (size_t)n * DD + c0);
    *(float4*)&t8[4] = *(const float4*)(g_t + (size_t)n * DD + c0 + 4);

    float m = -INFINITY, s = 0.f;
    float acc[8] = {};

    int e0 = g_off[n], e1 = g_off[n + 1];
    for (int e = e0; e < e1; e++) {
        int src = g_srcs[e];
        uint4 hv = *(const uint4*)(hhin + (size_t)src * DD + c0);
        uint4 uv = *(const uint4*)(g_ub + (size_t)src * DD + c0);

        const __nv_bfloat162* hp = (const __nv_bfloat162*)&hv;
        float hf[8];
        #pragma unroll
        for (int j = 0; j < 4; j++) {
            float2 f = __bfloat1622float2(hp[j]);
            hf[2 * j] = f.x; hf[2 * j + 1] = f.y;
        }
        float d = 0.f;
        #pragma unroll
        for (int j = 0; j < 8; j++) d += t8[j] * hf[j];
        #pragma unroll
        for (int o = 16; o > 0; o >>= 1) d += __shfl_xor_sync(0xffffffffu, d, o);
        d *= 0.0625f;

        float nm = fmaxf(m, d);
        float c = __expf(m - nm);
        float w = __expf(d - nm);
        s = s * c + w;
        m = nm;

        const __nv_bfloat162* up = (const __nv_bfloat162*)&uv;
        #pragma unroll
        for (int j = 0; j < 4; j++) {
            float2 f = __bfloat1622float2(up[j]);
            acc[2 * j]     = acc[2 * j]     * c + w * f.x;
            acc[2 * j + 1] = acc[2 * j + 1] * c + w * f.y;
        }
    }

    float inv = 1.0f / (s + 1e-9f);
    float hn[8], bb[8];
    *(float4*)&hn[0] = *(const float4*)(hin + (size_t)n * DD + c0);
    *(float4*)&hn[4] = *(const float4*)(hin + (size_t)n * DD + c0 + 4);
    *(float4*)&bb[0] = *(const float4*)(bpl + c0);
    *(float4*)&bb[4] = *(const float4*)(bpl + c0 + 4);

    float o8[8];
    #pragma unroll
    for (int j = 0; j < 8; j++)
        o8[j] = fmaxf(acc[j] * inv + bb[j] + hn[j], 0.f);

    *(float4*)(hout + (size_t)n * DD + c0)     = *(float4*)&o8[0];
    *(float4*)(hout + (size_t)n * DD + c0 + 4) = *(float4*)&o8[4];

    if (hhout) {
        bf16 hh8[8], hl8[8];
        #pragma unroll
        for (int j = 0; j < 8; j++) f32split(o8[j], hh8[j], hl8[j]);
        *(uint4*)(hhout + (size_t)n * DD + c0) = *(uint4*)&hh8[0];
        *(uint4*)(hlout + (size_t)n * DD + c0) = *(uint4*)&hl8[0];
    }
}

// ---------------- launch --------------------------------------------------------
extern "C" void kernel_launch(void* const* d_in, const int* in_sizes, int n_in,
                              void* d_out, int out_size)
{
    const float* x    = (const float*)d_in[0];
    const int*   edges= (const int*)  d_in[1];
    const float* w_in = (const float*)d_in[2];
    const float* b_in = (const float*)d_in[3];
    const float* wq   = (const float*)d_in[4];
    const float* wk   = (const float*)d_in[5];
    const float* wv   = (const float*)d_in[6];
    const float* wp   = (const float*)d_in[7];
    const float* bp   = (const float*)d_in[8];
    float* out = (float*)d_out;

    const int* src = edges;
    const int* dst = edges + NE;

    float *phA, *phB, *pt;
    bf16 *pub, *pxh, *pxl, *phhA, *phlA, *phhB, *phlB, *pwinh, *pwinl, *pMh, *pMl, *pWh, *pWl;
    cudaGetSymbolAddress((void**)&phA,   g_hA);
    cudaGetSymbolAddress((void**)&phB,   g_hB);
    cudaGetSymbolAddress((void**)&pt,    g_t);
    cudaGetSymbolAddress((void**)&pub,   g_ub);
    cudaGetSymbolAddress((void**)&pxh,   g_xh);
    cudaGetSymbolAddress((void**)&pxl,   g_xl);
    cudaGetSymbolAddress((void**)&phhA,  g_hhA);
    cudaGetSymbolAddress((void**)&phlA,  g_hlA);
    cudaGetSymbolAddress((void**)&phhB,  g_hhB);
    cudaGetSymbolAddress((void**)&phlB,  g_hlB);
    cudaGetSymbolAddress((void**)&pwinh, g_winh);
    cudaGetSymbolAddress((void**)&pwinl, g_winl);
    cudaGetSymbolAddress((void**)&pMh,   g_Mh);
    cudaGetSymbolAddress((void**)&pMl,   g_Ml);
    cudaGetSymbolAddress((void**)&pWh,   g_wvph);
    cudaGetSymbolAddress((void**)&pWl,   g_wvpl);

    static bool attr_set = false;
    if (!attr_set) {
        cudaFuncSetAttribute(k_mma<1>, cudaFuncAttributeMaxDynamicSharedMemorySize,
                             3 * ST_ELEMS * 2);
        cudaFuncSetAttribute(k_mma<0>, cudaFuncAttributeMaxDynamicSharedMemorySize,
                             3 * ST_ELEMS * 2);
        attr_set = true;
    }
    int shmem = 3 * ST_ELEMS * 2;

    // CSR build
    k_init   <<<(NN + 255) / 256, 256>>>();
    k_hist   <<<(NE + 255) / 256, 256>>>(dst);
    k_scan   <<<1, 1024>>>();
    k_scatter<<<(NE + 255) / 256, 256>>>(src, dst);

    // conversions + weight folding
    k_cvt<<<(NN * DD + 255) / 256, 256>>>(x, pxh, pxl, NN * DD);
    k_cvt<<<(DD * DD + 255) / 256, 256>>>(w_in, pwinh, pwinl, DD * DD);
    k_small<<<dim3(4, 4, 6), 256>>>(wq, wk, wv, wp, pMh, pMl, pWh, pWl);

    dim3 gg(2, 79);
    // h0 = relu(x @ w_in + b_in): fp32 + bf16 hi/lo
    k_mma<1><<<gg, 256, shmem>>>(pxh, pxl, pwinh, pwinl, phA, b_in, 1, phhA, phlA);

    float* cur = phA;  float* nxt = phB;
    bf16*  chh = phhA; bf16*  chl = phlA;
    bf16*  nhh = phhB; bf16*  nhl = phlB;
    for (int l = 0; l < NL; l++) {
        // t = h @ M  (fp32 out only), B-lo dropped
        k_mma<0><<<gg, 256, shmem>>>(chh, chl, pMh + l * DD * DD, nullptr,
                                     pt, nullptr, 0, nullptr, nullptr);
        // u = h @ wvp (bf16 out only), B-lo dropped
        k_mma<0><<<gg, 256, shmem>>>(chh, chl, pWh + l * DD * DD, nullptr,
                                     nullptr, nullptr, 0, pub, nullptr);
        float* ho = (l == NL - 1) ? out : nxt;
        bf16* oh = (l == NL - 1) ? nullptr : nhh;
        bf16* ol = (l == NL - 1) ? nullptr : nhl;
        k_edge<<<(NN * 32 + 255) / 256, 256>>>(cur, ho, bp + l * DD, chh, oh, ol);
        float* tf = cur; cur = nxt; nxt = tf;
        bf16* t1 = chh; chh = nhh; nhh = t1;
        bf16* t2 = chl; chl = nhl; nhl = t2;
    }
}

// round 5
// speedup vs baseline: 2.1888x; 1.1730x over previous
#include <cuda_runtime.h>
#include <cuda_bf16.h>
#include <stdint.h>
#include <math.h>

#define NN 10000
#define NE 320000
#define DD 256
#define NL 3

typedef __nv_bfloat16 bf16;
typedef unsigned int uint;

// ---------------- scratch -----------------------------------------------------
__device__ float g_t[NN * DD];
__device__ bf16  g_ub[NN * DD];                         // u in bf16
__device__ bf16  g_xh[NN * DD], g_xl[NN * DD];
__device__ bf16  g_hhA[NN * DD], g_hlA[NN * DD];        // bf16 h ping
__device__ bf16  g_hhB[NN * DD], g_hlB[NN * DD];        // bf16 h pong
__device__ bf16  g_winh[DD * DD], g_winl[DD * DD];
__device__ bf16  g_Mh[NL * DD * DD], g_Ml[NL * DD * DD];
__device__ bf16  g_wvph[NL * DD * DD], g_wvpl[NL * DD * DD];
__device__ int   g_deg[NN];
__device__ int   g_off[NN + 1];
__device__ int   g_cur[NN];
__device__ int   g_srcs[NE];

// ---------------- helpers -----------------------------------------------------
__device__ __forceinline__ void f32split(float v, bf16& h, bf16& l) {
    h = __float2bfloat16(v);
    l = __float2bfloat16(v - __bfloat162float(h));
}
__device__ __forceinline__ void ldsm4(uint& r0, uint& r1, uint& r2, uint& r3, uint addr) {
    asm volatile("ldmatrix.sync.aligned.m8n8.x4.shared.b16 {%0,%1,%2,%3}, [%4];"
                 : "=r"(r0), "=r"(r1), "=r"(r2), "=r"(r3) : "r"(addr));
}
__device__ __forceinline__ void ldsm4t(uint& r0, uint& r1, uint& r2, uint& r3, uint addr) {
    asm volatile("ldmatrix.sync.aligned.m8n8.x4.trans.shared.b16 {%0,%1,%2,%3}, [%4];"
                 : "=r"(r0), "=r"(r1), "=r"(r2), "=r"(r3) : "r"(addr));
}
__device__ __forceinline__ void mma_bf16(float* c, const uint* a, uint b0, uint b1) {
    asm volatile("mma.sync.aligned.m16n8k16.row.col.f32.bf16.bf16.f32 "
                 "{%0,%1,%2,%3},{%4,%5,%6,%7},{%8,%9},{%0,%1,%2,%3};"
                 : "+f"(c[0]), "+f"(c[1]), "+f"(c[2]), "+f"(c[3])
                 : "r"(a[0]), "r"(a[1]), "r"(a[2]), "r"(a[3]), "r"(b0), "r"(b1));
}
__device__ __forceinline__ void cp16(uint dst, const void* src) {
    asm volatile("cp.async.cg.shared.global [%0], [%1], 16;" :: "r"(dst), "l"(src));
}
__device__ __forceinline__ void cp16z(uint dst, const void* src, uint sz) {
    asm volatile("cp.async.cg.shared.global [%0], [%1], 16, %2;" :: "r"(dst), "l"(src), "r"(sz));
}
__device__ __forceinline__ void cp_commit() { asm volatile("cp.async.commit_group;"); }

// ---------------- CSR build ----------------------------------------------------
__global__ void k_init() {
    int i = blockIdx.x * blockDim.x + threadIdx.x;
    if (i < NN) { g_deg[i] = 0; g_cur[i] = 0; }
}
__global__ void k_hist(const int* __restrict__ dst) {
    int e = blockIdx.x * blockDim.x + threadIdx.x;
    if (e < NE) atomicAdd(&g_deg[dst[e]], 1);
}
__global__ void k_scan() {
    __shared__ int ws[32];
    int tid = threadIdx.x, lane = tid & 31, wid = tid >> 5;
    int carry = 0;
    for (int base = 0; base < NN; base += 1024) {
        int x = (base + tid < NN) ? g_deg[base + tid] : 0;
        int v = x;
        #pragma unroll
        for (int o = 1; o < 32; o <<= 1) {
            int y = __shfl_up_sync(0xffffffffu, v, o);
            if (lane >= o) v += y;
        }
        if (lane == 31) ws[wid] = v;
        __syncthreads();
        if (tid < 32) {
            int w = ws[tid];
            #pragma unroll
            for (int o = 1; o < 32; o <<= 1) {
                int y = __shfl_up_sync(0xffffffffu, w, o);
                if (tid >= o) w += y;
            }
            ws[tid] = w;
        }
        __syncthreads();
        int add = wid ? ws[wid - 1] : 0;
        if (base + tid < NN) g_off[base + tid] = carry + add + v - x;
        int tot = ws[31];
        __syncthreads();
        carry += tot;
    }
    if (tid == 0) g_off[NN] = carry;
}
__global__ void k_scatter(const int* __restrict__ src, const int* __restrict__ dst) {
    int e = blockIdx.x * blockDim.x + threadIdx.x;
    if (e < NE) {
        int d = dst[e];
        int pos = g_off[d] + atomicAdd(&g_cur[d], 1);
        g_srcs[pos] = src[e];
    }
}

// ---------------- fp32 -> bf16 hi/lo -------------------------------------------
__global__ void k_cvt(const float* __restrict__ in, bf16* __restrict__ h,
                      bf16* __restrict__ l, int n) {
    int i = blockIdx.x * blockDim.x + threadIdx.x;
    if (i < n) {
        bf16 hh, ll;
        f32split(in[i], hh, ll);
        h[i] = hh; l[i] = ll;
    }
}

// ---------------- weight folding ------------------------------------------------
__global__ __launch_bounds__(256) void k_small(
    const float* __restrict__ wq, const float* __restrict__ wk,
    const float* __restrict__ wv, const float* __restrict__ wp,
    bf16* __restrict__ pMh, bf16* __restrict__ pMl,
    bf16* __restrict__ pWh, bf16* __restrict__ pWl)
{
    int z = blockIdx.z;
    const float* A; const float* B; bf16* Ch; bf16* Cl; int tb;
    if (z < 3) { A = wq + z * DD * DD; B = wk + z * DD * DD;
                 Ch = pMh + z * DD * DD; Cl = pMl + z * DD * DD; tb = 1; }
    else       { A = wv + (z - 3) * DD * DD; B = wp + (z - 3) * DD * DD;
                 Ch = pWh + (z - 3) * DD * DD; Cl = pWl + (z - 3) * DD * DD; tb = 0; }

    __shared__ float As[16][65];
    __shared__ float Bs[16][65];
    int tid = threadIdx.x;
    int tx = tid & 15, ty = tid >> 4;
    int row0 = blockIdx.y * 64, col0 = blockIdx.x * 64;
    float acc[4][4] = {};

    for (int kt = 0; kt < DD; kt += 16) {
        {
            int r = tid >> 2, c = (tid & 3) * 4;
            float4 v = *(const float4*)(A + (row0 + r) * DD + kt + c);
            As[c + 0][r] = v.x; As[c + 1][r] = v.y; As[c + 2][r] = v.z; As[c + 3][r] = v.w;
        }
        if (tb) {
            int c = tid >> 2, k = (tid & 3) * 4;
            float4 v = *(const float4*)(B + (col0 + c) * DD + kt + k);
            Bs[k + 0][c] = v.x; Bs[k + 1][c] = v.y; Bs[k + 2][c] = v.z; Bs[k + 3][c] = v.w;
        } else {
            int k = tid >> 4, c = (tid & 15) * 4;
            float4 v = *(const float4*)(B + (kt + k) * DD + col0 + c);
            Bs[k][c + 0] = v.x; Bs[k][c + 1] = v.y; Bs[k][c + 2] = v.z; Bs[k][c + 3] = v.w;
        }
        __syncthreads();
        #pragma unroll
        for (int kk = 0; kk < 16; kk++) {
            float a[4], b[4];
            #pragma unroll
            for (int i = 0; i < 4; i++) { a[i] = As[kk][ty * 4 + i]; b[i] = Bs[kk][tx * 4 + i]; }
            #pragma unroll
            for (int i = 0; i < 4; i++)
                #pragma unroll
                for (int j = 0; j < 4; j++)
                    acc[i][j] += a[i] * b[j];
        }
        __syncthreads();
    }
    #pragma unroll
    for (int i = 0; i < 4; i++)
        #pragma unroll
        for (int j = 0; j < 4; j++) {
            bf16 h, l;
            f32split(acc[i][j], h, l);
            int idx = (row0 + ty * 4 + i) * DD + col0 + tx * 4 + j;
            Ch[idx] = h; Cl[idx] = l;
        }
}

// ---------------- h0 GEMM (full hi/lo precision), cp.async 3-stage -------------
// stage: Ah@0 (128x40), Al@5120, Bh@10240 (32x136), Bl@14592; ST1=18944 elems
#define ST1_ELEMS 18944
#define A_PITCH 40
#define B_PITCH 136

__global__ __launch_bounds__(256, 1) void k_mma_h0(
    const bf16* __restrict__ Ah, const bf16* __restrict__ Al,
    const bf16* __restrict__ Bh, const bf16* __restrict__ Bl,
    const float* __restrict__ bias,
    bf16* __restrict__ Chi, bf16* __restrict__ Clo)
{
    extern __shared__ __align__(16) bf16 smem[];
    int tid = threadIdx.x;
    int lane = tid & 31, warp = tid >> 5;
    int wm = warp & 1, wn = warp >> 1;
    int row0 = blockIdx.y * 128, col0 = blockIdx.x * 128;

    uint sbase = (uint)__cvta_generic_to_shared(smem);
    int a_r0 = tid >> 2,        a_c0 = (tid & 3) * 8;
    int a_r1 = (tid + 256) >> 2;
    int b_r0 = tid >> 4,        b_c0 = (tid & 15) * 8;
    int b_r1 = (tid + 256) >> 4;

    int ga0 = row0 + a_r0, ga1 = row0 + a_r1;
    uint sz0 = (ga0 < NN) ? 16u : 0u;
    uint sz1 = (ga1 < NN) ? 16u : 0u;
    int ca0 = (ga0 < NN) ? ga0 : 0;
    int ca1 = (ga1 < NN) ? ga1 : 0;

    auto issue = [&](int st, int kt) {
        uint base = sbase + (uint)(st * ST1_ELEMS) * 2u;
        uint dA0 = base + (uint)(a_r0 * A_PITCH + a_c0) * 2u;
        uint dA1 = base + (uint)(a_r1 * A_PITCH + a_c0) * 2u;
        cp16z(dA0,            Ah + (size_t)ca0 * DD + kt + a_c0, sz0);
        cp16z(dA1,            Ah + (size_t)ca1 * DD + kt + a_c0, sz1);
        cp16z(dA0 + 5120u*2u, Al + (size_t)ca0 * DD + kt + a_c0, sz0);
        cp16z(dA1 + 5120u*2u, Al + (size_t)ca1 * DD + kt + a_c0, sz1);
        uint dB0 = base + (10240u + (uint)(b_r0 * B_PITCH + b_c0)) * 2u;
        uint dB1 = base + (10240u + (uint)(b_r1 * B_PITCH + b_c0)) * 2u;
        cp16(dB0, Bh + (size_t)(kt + b_r0) * DD + col0 + b_c0);
        cp16(dB1, Bh + (size_t)(kt + b_r1) * DD + col0 + b_c0);
        cp16(dB0 + 4352u*2u, Bl + (size_t)(kt + b_r0) * DD + col0 + b_c0);
        cp16(dB1 + 4352u*2u, Bl + (size_t)(kt + b_r1) * DD + col0 + b_c0);
    };

    float acc[4][4][4] = {};
    issue(0, 0);   cp_commit();
    issue(1, 32);  cp_commit();

    #pragma unroll
    for (int i = 0; i < 8; i++) {
        if (i < 7) asm volatile("cp.async.wait_group 1;");
        else       asm volatile("cp.async.wait_group 0;");
        __syncthreads();
        if (i < 6) { issue((i + 2) % 3, (i + 2) * 32); cp_commit(); }

        int st = i % 3;
        uint base = sbase + (uint)(st * ST1_ELEMS) * 2u;
        uint aAh = base, aAl = base + 5120u * 2u;
        uint aBh = base + 10240u * 2u, aBl = base + 14592u * 2u;

        #pragma unroll
        for (int ks = 0; ks < 32; ks += 16) {
            int arow = lane & 15;
            int kcol = ks + ((lane >> 4) << 3);
            uint ah[4][4], al[4][4];
            #pragma unroll
            for (int mi = 0; mi < 4; mi++) {
                uint off = (uint)((wm * 64 + mi * 16 + arow) * A_PITCH + kcol) * 2u;
                ldsm4(ah[mi][0], ah[mi][1], ah[mi][2], ah[mi][3], aAh + off);
                ldsm4(al[mi][0], al[mi][1], al[mi][2], al[mi][3], aAl + off);
            }
            uint bhf[2][4], blf[2][4];
            int brow = ks + (lane & 15);
            #pragma unroll
            for (int ng = 0; ng < 2; ng++) {
                int bcol = wn * 32 + ng * 16 + ((lane >> 4) << 3);
                uint off = (uint)(brow * B_PITCH + bcol) * 2u;
                ldsm4t(bhf[ng][0], bhf[ng][1], bhf[ng][2], bhf[ng][3], aBh + off);
                ldsm4t(blf[ng][0], blf[ng][1], blf[ng][2], blf[ng][3], aBl + off);
            }
            #pragma unroll
            for (int mi = 0; mi < 4; mi++)
                #pragma unroll
                for (int ng = 0; ng < 2; ng++) {
                    mma_bf16(acc[mi][ng * 2],     ah[mi], bhf[ng][0], bhf[ng][1]);
                    mma_bf16(acc[mi][ng * 2 + 1], ah[mi], bhf[ng][2], bhf[ng][3]);
                    mma_bf16(acc[mi][ng * 2],     al[mi], bhf[ng][0], bhf[ng][1]);
                    mma_bf16(acc[mi][ng * 2 + 1], al[mi], bhf[ng][2], bhf[ng][3]);
                    mma_bf16(acc[mi][ng * 2],     ah[mi], blf[ng][0], blf[ng][1]);
                    mma_bf16(acc[mi][ng * 2 + 1], ah[mi], blf[ng][2], blf[ng][3]);
                }
        }
        __syncthreads();
    }

    int grp = lane >> 2, q = lane & 3;
    #pragma unroll
    for (int mi = 0; mi < 4; mi++) {
        int rb = row0 + wm * 64 + mi * 16 + grp;
        #pragma unroll
        for (int nj = 0; nj < 4; nj++) {
            int cb = col0 + wn * 32 + nj * 8 + q * 2;
            float b0 = bias[cb], b1 = bias[cb + 1];
            float v0 = fmaxf(acc[mi][nj][0] + b0, 0.f);
            float v1 = fmaxf(acc[mi][nj][1] + b1, 0.f);
            float v2 = fmaxf(acc[mi][nj][2] + b0, 0.f);
            float v3 = fmaxf(acc[mi][nj][3] + b1, 0.f);
            if (rb < NN) {
                size_t o = (size_t)rb * DD + cb;
                bf16 h0, l0, h1, l1;
                f32split(v0, h0, l0); f32split(v1, h1, l1);
                Chi[o] = h0; Chi[o + 1] = h1;
                Clo[o] = l0; Clo[o + 1] = l1;
            }
            if (rb + 8 < NN) {
                size_t o = (size_t)(rb + 8) * DD + cb;
                bf16 h2, l2, h3, l3;
                f32split(v2, h2, l2); f32split(v3, h3, l3);
                Chi[o] = h2; Chi[o + 1] = h3;
                Clo[o] = l2; Clo[o + 1] = l3;
            }
        }
    }
}

// ---------------- fused t+u GEMM (B-lo dropped), occ-2 -------------------------
// stage: Ah@0 (128x40), Al@5120, Bh@10240 (32x136); STU=14592 elems
#define STU_ELEMS 14592

__global__ __launch_bounds__(256, 2) void k_mma_tu(
    const bf16* __restrict__ Ah, const bf16* __restrict__ Al,
    const bf16* __restrict__ Mh, const bf16* __restrict__ Wh,
    float* __restrict__ t_out, bf16* __restrict__ u_out)
{
    extern __shared__ __align__(16) bf16 smem[];
    int bx = blockIdx.x;
    int half = bx >> 1;
    const bf16* Bh = half ? Wh : Mh;
    int col0 = (bx & 1) * 128;
    int row0 = blockIdx.y * 128;

    int tid = threadIdx.x;
    int lane = tid & 31, warp = tid >> 5;
    int wm = warp & 1, wn = warp >> 1;

    uint sbase = (uint)__cvta_generic_to_shared(smem);
    int a_r0 = tid >> 2,        a_c0 = (tid & 3) * 8;
    int a_r1 = (tid + 256) >> 2;
    int b_r0 = tid >> 4,        b_c0 = (tid & 15) * 8;
    int b_r1 = (tid + 256) >> 4;

    int ga0 = row0 + a_r0, ga1 = row0 + a_r1;
    uint sz0 = (ga0 < NN) ? 16u : 0u;
    uint sz1 = (ga1 < NN) ? 16u : 0u;
    int ca0 = (ga0 < NN) ? ga0 : 0;
    int ca1 = (ga1 < NN) ? ga1 : 0;

    auto issue = [&](int st, int kt) {
        uint base = sbase + (uint)(st * STU_ELEMS) * 2u;
        uint dA0 = base + (uint)(a_r0 * A_PITCH + a_c0) * 2u;
        uint dA1 = base + (uint)(a_r1 * A_PITCH + a_c0) * 2u;
        cp16z(dA0,            Ah + (size_t)ca0 * DD + kt + a_c0, sz0);
        cp16z(dA1,            Ah + (size_t)ca1 * DD + kt + a_c0, sz1);
        cp16z(dA0 + 5120u*2u, Al + (size_t)ca0 * DD + kt + a_c0, sz0);
        cp16z(dA1 + 5120u*2u, Al + (size_t)ca1 * DD + kt + a_c0, sz1);
        uint dB0 = base + (10240u + (uint)(b_r0 * B_PITCH + b_c0)) * 2u;
        uint dB1 = base + (10240u + (uint)(b_r1 * B_PITCH + b_c0)) * 2u;
        cp16(dB0, Bh + (size_t)(kt + b_r0) * DD + col0 + b_c0);
        cp16(dB1, Bh + (size_t)(kt + b_r1) * DD + col0 + b_c0);
    };

    float acc[4][4][4] = {};
    issue(0, 0);   cp_commit();
    issue(1, 32);  cp_commit();

    #pragma unroll
    for (int i = 0; i < 8; i++) {
        if (i < 7) asm volatile("cp.async.wait_group 1;");
        else       asm volatile("cp.async.wait_group 0;");
        __syncthreads();
        if (i < 6) { issue((i + 2) % 3, (i + 2) * 32); cp_commit(); }

        int st = i % 3;
        uint base = sbase + (uint)(st * STU_ELEMS) * 2u;
        uint aAh = base, aAl = base + 5120u * 2u;
        uint aBh = base + 10240u * 2u;

        #pragma unroll
        for (int ks = 0; ks < 32; ks += 16) {
            int arow = lane & 15;
            int kcol = ks + ((lane >> 4) << 3);
            uint ah[4][4], al[4][4];
            #pragma unroll
            for (int mi = 0; mi < 4; mi++) {
                uint off = (uint)((wm * 64 + mi * 16 + arow) * A_PITCH + kcol) * 2u;
                ldsm4(ah[mi][0], ah[mi][1], ah[mi][2], ah[mi][3], aAh + off);
                ldsm4(al[mi][0], al[mi][1], al[mi][2], al[mi][3], aAl + off);
            }
            uint bhf[2][4];
            int brow = ks + (lane & 15);
            #pragma unroll
            for (int ng = 0; ng < 2; ng++) {
                int bcol = wn * 32 + ng * 16 + ((lane >> 4) << 3);
                uint off = (uint)(brow * B_PITCH + bcol) * 2u;
                ldsm4t(bhf[ng][0], bhf[ng][1], bhf[ng][2], bhf[ng][3], aBh + off);
            }
            #pragma unroll
            for (int mi = 0; mi < 4; mi++)
                #pragma unroll
                for (int ng = 0; ng < 2; ng++) {
                    mma_bf16(acc[mi][ng * 2],     ah[mi], bhf[ng][0], bhf[ng][1]);
                    mma_bf16(acc[mi][ng * 2 + 1], ah[mi], bhf[ng][2], bhf[ng][3]);
                    mma_bf16(acc[mi][ng * 2],     al[mi], bhf[ng][0], bhf[ng][1]);
                    mma_bf16(acc[mi][ng * 2 + 1], al[mi], bhf[ng][2], bhf[ng][3]);
                }
        }
        __syncthreads();
    }

    int grp = lane >> 2, q = lane & 3;
    #pragma unroll
    for (int mi = 0; mi < 4; mi++) {
        int rb = row0 + wm * 64 + mi * 16 + grp;
        #pragma unroll
        for (int nj = 0; nj < 4; nj++) {
            int cb = col0 + wn * 32 + nj * 8 + q * 2;
            float v0 = acc[mi][nj][0], v1 = acc[mi][nj][1];
            float v2 = acc[mi][nj][2], v3 = acc[mi][nj][3];
            if (half == 0) {
                if (rb < NN) {
                    size_t o = (size_t)rb * DD + cb;
                    t_out[o] = v0; t_out[o + 1] = v1;
                }
                if (rb + 8 < NN) {
                    size_t o = (size_t)(rb + 8) * DD + cb;
                    t_out[o] = v2; t_out[o + 1] = v3;
                }
            } else {
                if (rb < NN) {
                    size_t o = (size_t)rb * DD + cb;
                    u_out[o] = __float2bfloat16(v0);
                    u_out[o + 1] = __float2bfloat16(v1);
                }
                if (rb + 8 < NN) {
                    size_t o = (size_t)(rb + 8) * DD + cb;
                    u_out[o] = __float2bfloat16(v2);
                    u_out[o + 1] = __float2bfloat16(v3);
                }
            }
        }
    }
}

// ---------------- per-node online-softmax aggregation ---------------------------
__global__ __launch_bounds__(256) void k_edge(
    float* __restrict__ out_f32,
    const float* __restrict__ bpl,
    const bf16* __restrict__ hhin, const bf16* __restrict__ hlin,
    bf16* __restrict__ hhout, bf16* __restrict__ hlout)
{
    int gw = (blockIdx.x * blockDim.x + threadIdx.x) >> 5;
    int lane = threadIdx.x & 31;
    if (gw >= NN) return;
    int n = gw;
    int c0 = lane * 8;

    float t8[8];
    *(float4*)&t8[0] = *(const float4*)(g_t + (size_t)n * DD + c0);
    *(float4*)&t8[4] = *(const float4*)(g_t + (size_t)n * DD + c0 + 4);

    float m = -INFINITY, s = 0.f;
    float acc[8] = {};

    int e0 = g_off[n], e1 = g_off[n + 1];
    uint4 hvN, uvN;
    if (e0 < e1) {
        int sN = g_srcs[e0];
        hvN = *(const uint4*)(hhin + (size_t)sN * DD + c0);
        uvN = *(const uint4*)(g_ub + (size_t)sN * DD + c0);
    }
    for (int e = e0; e < e1; e++) {
        uint4 hv = hvN, uv = uvN;
        if (e + 1 < e1) {
            int sN = g_srcs[e + 1];
            hvN = *(const uint4*)(hhin + (size_t)sN * DD + c0);
            uvN = *(const uint4*)(g_ub + (size_t)sN * DD + c0);
        }

        const __nv_bfloat162* hp = (const __nv_bfloat162*)&hv;
        float d = 0.f;
        #pragma unroll
        for (int j = 0; j < 4; j++) {
            float2 f = __bfloat1622float2(hp[j]);
            d += t8[2 * j] * f.x + t8[2 * j + 1] * f.y;
        }
        #pragma unroll
        for (int o = 16; o > 0; o >>= 1) d += __shfl_xor_sync(0xffffffffu, d, o);
        d *= 0.0625f;

        float nm = fmaxf(m, d);
        float c = __expf(m - nm);
        float w = __expf(d - nm);
        s = s * c + w;
        m = nm;

        const __nv_bfloat162* up = (const __nv_bfloat162*)&uv;
        #pragma unroll
        for (int j = 0; j < 4; j++) {
            float2 f = __bfloat1622float2(up[j]);
            acc[2 * j]     = acc[2 * j]     * c + w * f.x;
            acc[2 * j + 1] = acc[2 * j + 1] * c + w * f.y;
        }
    }

    float inv = 1.0f / (s + 1e-9f);

    // residual from exact hi/lo split
    uint4 hh4 = *(const uint4*)(hhin + (size_t)n * DD + c0);
    uint4 hl4 = *(const uint4*)(hlin + (size_t)n * DD + c0);
    const __nv_bfloat162* hhp = (const __nv_bfloat162*)&hh4;
    const __nv_bfloat162* hlp = (const __nv_bfloat162*)&hl4;
    float hn[8];
    #pragma unroll
    for (int j = 0; j < 4; j++) {
        float2 a = __bfloat1622float2(hhp[j]);
        float2 b = __bfloat1622float2(hlp[j]);
        hn[2 * j] = a.x + b.x; hn[2 * j + 1] = a.y + b.y;
    }
    float bb[8];
    *(float4*)&bb[0] = *(const float4*)(bpl + c0);
    *(float4*)&bb[4] = *(const float4*)(bpl + c0 + 4);

    float o8[8];
    #pragma unroll
    for (int j = 0; j < 8; j++)
        o8[j] = fmaxf(acc[j] * inv + bb[j] + hn[j], 0.f);

    if (out_f32) {
        *(float4*)(out_f32 + (size_t)n * DD + c0)     = *(float4*)&o8[0];
        *(float4*)(out_f32 + (size_t)n * DD + c0 + 4) = *(float4*)&o8[4];
    }
    if (hhout) {
        bf16 hh8[8], hl8[8];
        #pragma unroll
        for (int j = 0; j < 8; j++) f32split(o8[j], hh8[j], hl8[j]);
        *(uint4*)(hhout + (size_t)n * DD + c0) = *(uint4*)&hh8[0];
        *(uint4*)(hlout + (size_t)n * DD + c0) = *(uint4*)&hl8[0];
    }
}

// ---------------- launch ----------------------------------------------------------
extern "C" void kernel_launch(void* const* d_in, const int* in_sizes, int n_in,
                              void* d_out, int out_size)
{
    const float* x    = (const float*)d_in[0];
    const int*   edges= (const int*)  d_in[1];
    const float* w_in = (const float*)d_in[2];
    const float* b_in = (const float*)d_in[3];
    const float* wq   = (const float*)d_in[4];
    const float* wk   = (const float*)d_in[5];
    const float* wv   = (const float*)d_in[6];
    const float* wp   = (const float*)d_in[7];
    const float* bp   = (const float*)d_in[8];
    float* out = (float*)d_out;

    const int* src = edges;
    const int* dst = edges + NE;

    float *pt;
    bf16 *pub, *pxh, *pxl, *phhA, *phlA, *phhB, *phlB, *pwinh, *pwinl, *pMh, *pMl, *pWh, *pWl;
    cudaGetSymbolAddress((void**)&pt,    g_t);
    cudaGetSymbolAddress((void**)&pub,   g_ub);
    cudaGetSymbolAddress((void**)&pxh,   g_xh);
    cudaGetSymbolAddress((void**)&pxl,   g_xl);
    cudaGetSymbolAddress((void**)&phhA,  g_hhA);
    cudaGetSymbolAddress((void**)&phlA,  g_hlA);
    cudaGetSymbolAddress((void**)&phhB,  g_hhB);
    cudaGetSymbolAddress((void**)&phlB,  g_hlB);
    cudaGetSymbolAddress((void**)&pwinh, g_winh);
    cudaGetSymbolAddress((void**)&pwinl, g_winl);
    cudaGetSymbolAddress((void**)&pMh,   g_Mh);
    cudaGetSymbolAddress((void**)&pMl,   g_Ml);
    cudaGetSymbolAddress((void**)&pWh,   g_wvph);
    cudaGetSymbolAddress((void**)&pWl,   g_wvpl);

    static bool attr_set = false;
    if (!attr_set) {
        cudaFuncSetAttribute(k_mma_h0, cudaFuncAttributeMaxDynamicSharedMemorySize,
                             3 * ST1_ELEMS * 2);
        cudaFuncSetAttribute(k_mma_tu, cudaFuncAttributeMaxDynamicSharedMemorySize,
                             3 * STU_ELEMS * 2);
        attr_set = true;
    }

    // conversions + weight folding first (so profile slot lands on k_mma_h0)
    k_cvt<<<(NN * DD + 255) / 256, 256>>>(x, pxh, pxl, NN * DD);
    k_cvt<<<(DD * DD + 255) / 256, 256>>>(w_in, pwinh, pwinl, DD * DD);
    k_small<<<dim3(4, 4, 6), 256>>>(wq, wk, wv, wp, pMh, pMl, pWh, pWl);

    // h0 = relu(x @ w_in + b_in) -> bf16 hi/lo only
    k_mma_h0<<<dim3(2, 79), 256, 3 * ST1_ELEMS * 2>>>(
        pxh, pxl, pwinh, pwinl, b_in, phhA, phlA);

    // CSR build (independent of h0 pipeline)
    k_init   <<<(NN + 255) / 256, 256>>>();
    k_hist   <<<(NE + 255) / 256, 256>>>(dst);
    k_scan   <<<1, 1024>>>();
    k_scatter<<<(NE + 255) / 256, 256>>>(src, dst);

    bf16* chh = phhA; bf16* chl = phlA;
    bf16* nhh = phhB; bf16* nhl = phlB;
    for (int l = 0; l < NL; l++) {
        k_mma_tu<<<dim3(4, 79), 256, 3 * STU_ELEMS * 2>>>(
            chh, chl, pMh + l * DD * DD, pWh + l * DD * DD, pt, pub);
        float* ho = (l == NL - 1) ? out : nullptr;
        bf16* oh = (l == NL - 1) ? nullptr : nhh;
        bf16* ol = (l == NL - 1) ? nullptr : nhl;
        k_edge<<<(NN * 32 + 255) / 256, 256>>>(ho, bp + l * DD, chh, chl, oh, ol);
        bf16* t1 = chh; chh = nhh; nhh = t1;
        bf16* t2 = chl; chl = nhl; nhl = t2;
    }
}